// round 1
// baseline (speedup 1.0000x reference)
#include <cuda_runtime.h>

#define NN 100000
#define EE 1000000
#define DD 128
#define CAP 96
#define BM 64
#define BK 32

// ---------------- scratch (static device globals; no allocation) ----------------
__device__ __align__(128) float g_bufA[NN * DD];   // h buffer (layer outputs)
__device__ __align__(128) float g_bufB[NN * DD];   // hs buffer (GEMM outputs)
__device__ int   g_adj[NN * CAP];                  // padded adjacency: incoming srcs per dst
__device__ int   g_deg_out[NN];
__device__ int   g_cnt[NN];                        // in-degree / fill counter
__device__ float g_norm_src[NN];
__device__ float g_norm_dst[NN];
__device__ __align__(16) float g_cs[3 * DD];       // fused per-col scale  (BN folded)
__device__ __align__(16) float g_cb[3 * DD];       // fused per-col shift

// ---------------- graph preprocessing ----------------
__global__ void k_init() {
    int i = blockIdx.x * blockDim.x + threadIdx.x;
    if (i < NN) { g_deg_out[i] = 0; g_cnt[i] = 0; }
}

__global__ void k_build(const int* __restrict__ es, const int* __restrict__ ed) {
    int i = blockIdx.x * blockDim.x + threadIdx.x;
    if (i < EE) {
        int s = es[i], d = ed[i];
        atomicAdd(&g_deg_out[s], 1);
        int slot = atomicAdd(&g_cnt[d], 1);
        if (slot < CAP) g_adj[d * CAP + slot] = s;
    }
}

__global__ void k_norm() {
    int i = blockIdx.x * blockDim.x + threadIdx.x;
    if (i < NN) {
        int dout = g_deg_out[i]; if (dout < 1) dout = 1;
        int din  = g_cnt[i];     if (din  < 1) din  = 1;
        g_norm_src[i] = rsqrtf((float)dout);
        g_norm_dst[i] = rsqrtf((float)din);
    }
}

// Fold bias + BN(eval) into per-column scale/shift:
//   layer<2: y = relu((agg*nd + b - m) * g*rsqrt(v+eps) + beta)
//          = relu(agg*nd*cs + cb),  cs = g*rsqrt(v+eps), cb = (b-m)*cs + beta
//   layer2:  cs = 1, cb = b2
__global__ void k_prep(const float* __restrict__ b0, const float* __restrict__ g0,
                       const float* __restrict__ be0, const float* __restrict__ m0,
                       const float* __restrict__ v0,
                       const float* __restrict__ b1, const float* __restrict__ g1,
                       const float* __restrict__ be1, const float* __restrict__ m1,
                       const float* __restrict__ v1,
                       const float* __restrict__ b2) {
    int j = threadIdx.x;
    if (j < DD) {
        float s0 = g0[j] * rsqrtf(v0[j] + 1e-5f);
        g_cs[j] = s0;
        g_cb[j] = (b0[j] - m0[j]) * s0 + be0[j];
        float s1 = g1[j] * rsqrtf(v1[j] + 1e-5f);
        g_cs[DD + j] = s1;
        g_cb[DD + j] = (b1[j] - m1[j]) * s1 + be1[j];
        g_cs[2 * DD + j] = 1.0f;
        g_cb[2 * DD + j] = b2[j];
    }
}

// ---------------- GEMM: out[n, j] = (in[n, :] * norm_src[n]) @ W ----------------
// Block computes BM x 128 tile. 256 threads, each 4 rows x 8 cols.
__global__ __launch_bounds__(256) void k_gemm(const float* __restrict__ A,
                                              const float* __restrict__ W,
                                              float* __restrict__ C) {
    __shared__ float As[BM][BK];
    __shared__ float Bs[BK][DD];

    int tid  = threadIdx.x;
    int row0 = blockIdx.x * BM;
    int ty   = tid >> 4;   // 0..15 -> rows ty*4
    int tx   = tid & 15;   // 0..15 -> cols tx*8

    float acc[4][8];
#pragma unroll
    for (int r = 0; r < 4; r++)
#pragma unroll
        for (int c = 0; c < 8; c++) acc[r][c] = 0.f;

    for (int k0 = 0; k0 < DD; k0 += BK) {
        // load A tile (rows scaled by norm_src): 64x32 floats, 2 float4 per thread
#pragma unroll
        for (int it = 0; it < 2; it++) {
            int r = (tid >> 3) + it * 32;     // 0..63
            int c = (tid & 7) * 4;            // 0..28
            int grow = row0 + r;
            int gr = (grow < NN) ? grow : (NN - 1);
            float4 v = *(const float4*)&A[(long)gr * DD + k0 + c];
            float s = g_norm_src[gr];
            v.x *= s; v.y *= s; v.z *= s; v.w *= s;
            *(float4*)&As[r][c] = v;
        }
        // load B tile: 32x128 floats, 4 float4 per thread
#pragma unroll
        for (int it = 0; it < 4; it++) {
            int k = (tid >> 5) + it * 8;      // 0..31
            int j = (tid & 31) * 4;           // 0..124
            *(float4*)&Bs[k][j] = *(const float4*)&W[(k0 + k) * DD + j];
        }
        __syncthreads();

#pragma unroll
        for (int kk = 0; kk < BK; kk++) {
            float a[4];
#pragma unroll
            for (int r = 0; r < 4; r++) a[r] = As[ty * 4 + r][kk];
            float4 bb0 = *(const float4*)&Bs[kk][tx * 8];
            float4 bb1 = *(const float4*)&Bs[kk][tx * 8 + 4];
            float b[8] = {bb0.x, bb0.y, bb0.z, bb0.w, bb1.x, bb1.y, bb1.z, bb1.w};
#pragma unroll
            for (int r = 0; r < 4; r++)
#pragma unroll
                for (int c = 0; c < 8; c++) acc[r][c] += a[r] * b[c];
        }
        __syncthreads();
    }

#pragma unroll
    for (int r = 0; r < 4; r++) {
        int grow = row0 + ty * 4 + r;
        if (grow < NN) {
            float4 o0 = {acc[r][0], acc[r][1], acc[r][2], acc[r][3]};
            float4 o1 = {acc[r][4], acc[r][5], acc[r][6], acc[r][7]};
            *(float4*)&C[(long)grow * DD + tx * 8]     = o0;
            *(float4*)&C[(long)grow * DD + tx * 8 + 4] = o1;
        }
    }
}

// ---------------- Aggregate + fused epilogue: one warp per dst node ----------------
__global__ __launch_bounds__(256) void k_agg(int layer, const float* __restrict__ hs,
                                             float* __restrict__ out, int relu) {
    int w    = (blockIdx.x * blockDim.x + threadIdx.x) >> 5;
    int lane = threadIdx.x & 31;
    if (w >= NN) return;

    const float4* hs4 = (const float4*)hs;
    int cnt = g_cnt[w]; if (cnt > CAP) cnt = CAP;
    const int* lst = &g_adj[w * CAP];

    float4 acc = make_float4(0.f, 0.f, 0.f, 0.f);
    int e = 0;
    // MLP=4: batch 4 gathers per iteration
    for (; e + 4 <= cnt; e += 4) {
        int s0 = lst[e], s1 = lst[e + 1], s2 = lst[e + 2], s3 = lst[e + 3];
        float4 v0 = hs4[s0 * 32 + lane];
        float4 v1 = hs4[s1 * 32 + lane];
        float4 v2 = hs4[s2 * 32 + lane];
        float4 v3 = hs4[s3 * 32 + lane];
        acc.x += (v0.x + v1.x) + (v2.x + v3.x);
        acc.y += (v0.y + v1.y) + (v2.y + v3.y);
        acc.z += (v0.z + v1.z) + (v2.z + v3.z);
        acc.w += (v0.w + v1.w) + (v2.w + v3.w);
    }
    for (; e < cnt; e++) {
        int s = lst[e];
        float4 v = hs4[s * 32 + lane];
        acc.x += v.x; acc.y += v.y; acc.z += v.z; acc.w += v.w;
    }

    float nd = g_norm_dst[w];
    int jb = layer * DD + lane * 4;
    float4 cs = *(const float4*)&g_cs[jb];
    float4 cb = *(const float4*)&g_cb[jb];
    float4 r;
    r.x = acc.x * nd * cs.x + cb.x;
    r.y = acc.y * nd * cs.y + cb.y;
    r.z = acc.z * nd * cs.z + cb.z;
    r.w = acc.w * nd * cs.w + cb.w;
    if (relu) {
        r.x = fmaxf(r.x, 0.f); r.y = fmaxf(r.y, 0.f);
        r.z = fmaxf(r.z, 0.f); r.w = fmaxf(r.w, 0.f);
    }
    ((float4*)out)[w * 32 + lane] = r;
}

// ---------------- launch ----------------
extern "C" void kernel_launch(void* const* d_in, const int* in_sizes, int n_in,
                              void* d_out, int out_size) {
    const float* x   = (const float*)d_in[0];
    const int*   es  = (const int*)d_in[1];
    const int*   ed  = (const int*)d_in[2];
    const float* W0  = (const float*)d_in[3];
    const float* b0  = (const float*)d_in[4];
    const float* W1  = (const float*)d_in[5];
    const float* b1  = (const float*)d_in[6];
    const float* W2  = (const float*)d_in[7];
    const float* b2  = (const float*)d_in[8];
    const float* g0  = (const float*)d_in[9];
    const float* be0 = (const float*)d_in[10];
    const float* m0  = (const float*)d_in[11];
    const float* v0  = (const float*)d_in[12];
    const float* g1  = (const float*)d_in[13];
    const float* be1 = (const float*)d_in[14];
    const float* m1  = (const float*)d_in[15];
    const float* v1  = (const float*)d_in[16];

    float *bufA, *bufB;
    cudaGetSymbolAddress((void**)&bufA, g_bufA);
    cudaGetSymbolAddress((void**)&bufB, g_bufB);

    k_init<<<(NN + 255) / 256, 256>>>();
    k_build<<<(EE + 255) / 256, 256>>>(es, ed);
    k_norm<<<(NN + 255) / 256, 256>>>();
    k_prep<<<1, 128>>>(b0, g0, be0, m0, v0, b1, g1, be1, m1, v1, b2);

    int gemm_blocks = (NN + BM - 1) / BM;
    int agg_blocks  = (NN + 7) / 8;  // 8 warps per 256-thread block, warp per node

    // layer 0
    k_gemm<<<gemm_blocks, 256>>>(x, W0, bufB);
    k_agg<<<agg_blocks, 256>>>(0, bufB, bufA, 1);
    // layer 1
    k_gemm<<<gemm_blocks, 256>>>(bufA, W1, bufB);
    k_agg<<<agg_blocks, 256>>>(1, bufB, bufA, 1);
    // layer 2 (no BN / no ReLU), write final output
    k_gemm<<<gemm_blocks, 256>>>(bufA, W2, bufB);
    k_agg<<<agg_blocks, 256>>>(2, bufB, (float*)d_out, 0);
}

// round 3
// speedup vs baseline: 2.1345x; 2.1345x over previous
#include <cuda_runtime.h>

#define NN 100000
#define EE 1000000
#define DD 128
#define CAP 96

// GEMM tiling
#define BM 128
#define BK 32
#define AS_STRIDE 36    // conflict-free A-frag reads
#define BS_STRIDE 136   // conflict-free B-frag reads

// ---------------- scratch (static device globals; no allocation) ----------------
__device__ __align__(128) float g_bufA[NN * DD];   // h buffer (layer outputs)
__device__ __align__(128) float g_bufB[NN * DD];   // hs buffer (GEMM outputs)
__device__ int   g_adj[NN * CAP];                  // padded adjacency: incoming srcs per dst
__device__ int   g_deg_out[NN];
__device__ int   g_cnt[NN];                        // in-degree / fill counter
__device__ float g_norm_src[NN];
__device__ float g_norm_dst[NN];
__device__ __align__(16) float g_cs[3 * DD];       // fused per-col scale  (BN folded)
__device__ __align__(16) float g_cb[3 * DD];       // fused per-col shift

// ---------------- graph preprocessing ----------------
__global__ void k_build(const int* __restrict__ es, const int* __restrict__ ed) {
    int i = (blockIdx.x * blockDim.x + threadIdx.x) * 2;
#pragma unroll
    for (int t = 0; t < 2; t++) {
        int e = i + t;
        if (e < EE) {
            int s = es[e], d = ed[e];
            atomicAdd(&g_deg_out[s], 1);
            int slot = atomicAdd(&g_cnt[d], 1);
            if (slot < CAP) g_adj[d * CAP + slot] = s;
        }
    }
}

__global__ void k_norm() {
    int i = blockIdx.x * blockDim.x + threadIdx.x;
    if (i < NN) {
        int dout = g_deg_out[i]; if (dout < 1) dout = 1;
        int din  = g_cnt[i];     if (din  < 1) din  = 1;
        g_norm_src[i] = rsqrtf((float)dout);
        g_norm_dst[i] = rsqrtf((float)din);
    }
}

__global__ void k_prep(const float* __restrict__ b0, const float* __restrict__ g0,
                       const float* __restrict__ be0, const float* __restrict__ m0,
                       const float* __restrict__ v0,
                       const float* __restrict__ b1, const float* __restrict__ g1,
                       const float* __restrict__ be1, const float* __restrict__ m1,
                       const float* __restrict__ v1,
                       const float* __restrict__ b2) {
    int j = threadIdx.x;
    if (j < DD) {
        float s0 = g0[j] * rsqrtf(v0[j] + 1e-5f);
        g_cs[j] = s0;
        g_cb[j] = (b0[j] - m0[j]) * s0 + be0[j];
        float s1 = g1[j] * rsqrtf(v1[j] + 1e-5f);
        g_cs[DD + j] = s1;
        g_cb[DD + j] = (b1[j] - m1[j]) * s1 + be1[j];
        g_cs[2 * DD + j] = 1.0f;
        g_cb[2 * DD + j] = b2[j];
    }
}

// ---------------- tf32 helpers ----------------
__device__ __forceinline__ unsigned f2tf32(float v) {
    unsigned u;
    asm("cvt.rna.tf32.f32 %0, %1;" : "=r"(u) : "f"(v));
    return u;
}

__device__ __forceinline__ void mma_tf32(float c[4], const unsigned a[4], const unsigned b[2]) {
    asm volatile(
        "mma.sync.aligned.m16n8k8.row.col.f32.tf32.tf32.f32 "
        "{%0,%1,%2,%3}, {%4,%5,%6,%7}, {%8,%9}, {%0,%1,%2,%3};"
        : "+f"(c[0]), "+f"(c[1]), "+f"(c[2]), "+f"(c[3])
        : "r"(a[0]), "r"(a[1]), "r"(a[2]), "r"(a[3]), "r"(b[0]), "r"(b[1]));
}

// ---------------- GEMM (tf32 tensor cores): C[n,j] = (A[n,:]*norm_src[n]) @ W ----------------
// Block: 128 rows x 128 cols. 8 warps in 4x2 grid, each warp 32x64.
__global__ __launch_bounds__(256) void k_gemm(const float* __restrict__ A,
                                              const float* __restrict__ W,
                                              float* __restrict__ C) {
    __shared__ unsigned As[BM * AS_STRIDE];       // tf32 bits, [row][k] stride 36
    __shared__ unsigned Bs[BK * BS_STRIDE];       // tf32 bits, [k][col] stride 136

    int tid  = threadIdx.x;
    int lane = tid & 31;
    int warp = tid >> 5;
    int wr   = warp >> 1;          // 0..3
    int wc   = warp & 1;           // 0..1
    int g    = lane >> 2;          // 0..7
    int tig  = lane & 3;           // 0..3
    int row0 = blockIdx.x * BM;
    int rm   = wr * 32;
    int cbase = wc * 64;

    float acc[2][8][4];
#pragma unroll
    for (int t = 0; t < 2; t++)
#pragma unroll
        for (int c = 0; c < 8; c++)
#pragma unroll
            for (int r = 0; r < 4; r++) acc[t][c][r] = 0.f;

    for (int k0 = 0; k0 < DD; k0 += BK) {
        // --- load A tile 128x32 (scaled by norm_src, converted to tf32) ---
#pragma unroll
        for (int it = 0; it < 4; it++) {
            int f   = tid + it * 256;       // float4 index, 1024 total
            int r   = f >> 3;               // 0..127
            int c4  = (f & 7) * 4;          // 0..28
            int grow = row0 + r;
            int gr = (grow < NN) ? grow : (NN - 1);
            float4 v = *(const float4*)&A[(long)gr * DD + k0 + c4];
            float s = g_norm_src[gr];
            unsigned* dst = &As[r * AS_STRIDE + c4];
            dst[0] = f2tf32(v.x * s);
            dst[1] = f2tf32(v.y * s);
            dst[2] = f2tf32(v.z * s);
            dst[3] = f2tf32(v.w * s);
        }
        // --- load B tile 32x128 (tf32) ---
#pragma unroll
        for (int it = 0; it < 4; it++) {
            int f  = tid + it * 256;
            int r  = f >> 5;                // 0..31
            int c4 = (f & 31) * 4;          // 0..124
            float4 v = *(const float4*)&W[(k0 + r) * DD + c4];
            unsigned* dst = &Bs[r * BS_STRIDE + c4];
            dst[0] = f2tf32(v.x);
            dst[1] = f2tf32(v.y);
            dst[2] = f2tf32(v.z);
            dst[3] = f2tf32(v.w);
        }
        __syncthreads();

#pragma unroll
        for (int ks = 0; ks < 4; ks++) {
            int kk = ks * 8;
            // A fragments: 2 row tiles of m16
            unsigned af[2][4];
#pragma unroll
            for (int t = 0; t < 2; t++) {
                int rbase = rm + t * 16 + g;
                af[t][0] = As[(rbase)     * AS_STRIDE + kk + tig];
                af[t][1] = As[(rbase + 8) * AS_STRIDE + kk + tig];
                af[t][2] = As[(rbase)     * AS_STRIDE + kk + tig + 4];
                af[t][3] = As[(rbase + 8) * AS_STRIDE + kk + tig + 4];
            }
            // B fragments: 8 col tiles of n8
            unsigned bf[8][2];
#pragma unroll
            for (int c = 0; c < 8; c++) {
                int col = cbase + c * 8 + g;
                bf[c][0] = Bs[(kk + tig)     * BS_STRIDE + col];
                bf[c][1] = Bs[(kk + tig + 4) * BS_STRIDE + col];
            }
#pragma unroll
            for (int t = 0; t < 2; t++)
#pragma unroll
                for (int c = 0; c < 8; c++)
                    mma_tf32(acc[t][c], af[t], bf[c]);
        }
        __syncthreads();
    }

    // --- epilogue: write C ---
#pragma unroll
    for (int t = 0; t < 2; t++) {
        int r_lo = row0 + rm + t * 16 + g;
        int r_hi = r_lo + 8;
#pragma unroll
        for (int c = 0; c < 8; c++) {
            int col = cbase + c * 8 + 2 * tig;
            if (r_lo < NN) {
                float2 v = {acc[t][c][0], acc[t][c][1]};
                *(float2*)&C[(long)r_lo * DD + col] = v;
            }
            if (r_hi < NN) {
                float2 v = {acc[t][c][2], acc[t][c][3]};
                *(float2*)&C[(long)r_hi * DD + col] = v;
            }
        }
    }
}

// ---------------- Aggregate + fused epilogue: one warp per dst node ----------------
__global__ __launch_bounds__(256) void k_agg(int layer, const float* __restrict__ hs,
                                             float* __restrict__ out, int relu) {
    int w    = (blockIdx.x * blockDim.x + threadIdx.x) >> 5;
    int lane = threadIdx.x & 31;
    if (w >= NN) return;

    const float4* hs4 = (const float4*)hs;
    int cnt = g_cnt[w]; if (cnt > CAP) cnt = CAP;
    const int* lst = &g_adj[w * CAP];

    float4 acc = make_float4(0.f, 0.f, 0.f, 0.f);
    int e = 0;
    for (; e + 4 <= cnt; e += 4) {
        int s0 = lst[e], s1 = lst[e + 1], s2 = lst[e + 2], s3 = lst[e + 3];
        float4 v0 = hs4[s0 * 32 + lane];
        float4 v1 = hs4[s1 * 32 + lane];
        float4 v2 = hs4[s2 * 32 + lane];
        float4 v3 = hs4[s3 * 32 + lane];
        acc.x += (v0.x + v1.x) + (v2.x + v3.x);
        acc.y += (v0.y + v1.y) + (v2.y + v3.y);
        acc.z += (v0.z + v1.z) + (v2.z + v3.z);
        acc.w += (v0.w + v1.w) + (v2.w + v3.w);
    }
    for (; e < cnt; e++) {
        int s = lst[e];
        float4 v = hs4[s * 32 + lane];
        acc.x += v.x; acc.y += v.y; acc.z += v.z; acc.w += v.w;
    }

    float nd = g_norm_dst[w];
    int jb = layer * DD + lane * 4;
    float4 cs = *(const float4*)&g_cs[jb];
    float4 cb = *(const float4*)&g_cb[jb];
    float4 r;
    r.x = acc.x * nd * cs.x + cb.x;
    r.y = acc.y * nd * cs.y + cb.y;
    r.z = acc.z * nd * cs.z + cb.z;
    r.w = acc.w * nd * cs.w + cb.w;
    if (relu) {
        r.x = fmaxf(r.x, 0.f); r.y = fmaxf(r.y, 0.f);
        r.z = fmaxf(r.z, 0.f); r.w = fmaxf(r.w, 0.f);
    }
    ((float4*)out)[w * 32 + lane] = r;
}

// ---------------- launch ----------------
extern "C" void kernel_launch(void* const* d_in, const int* in_sizes, int n_in,
                              void* d_out, int out_size) {
    const float* x   = (const float*)d_in[0];
    const int*   es  = (const int*)d_in[1];
    const int*   ed  = (const int*)d_in[2];
    const float* W0  = (const float*)d_in[3];
    const float* b0  = (const float*)d_in[4];
    const float* W1  = (const float*)d_in[5];
    const float* b1  = (const float*)d_in[6];
    const float* W2  = (const float*)d_in[7];
    const float* b2  = (const float*)d_in[8];
    const float* g0  = (const float*)d_in[9];
    const float* be0 = (const float*)d_in[10];
    const float* m0  = (const float*)d_in[11];
    const float* v0  = (const float*)d_in[12];
    const float* g1  = (const float*)d_in[13];
    const float* be1 = (const float*)d_in[14];
    const float* m1  = (const float*)d_in[15];
    const float* v1  = (const float*)d_in[16];

    float *bufA, *bufB, *degOut, *cnt;
    cudaGetSymbolAddress((void**)&bufA, g_bufA);
    cudaGetSymbolAddress((void**)&bufB, g_bufB);
    cudaGetSymbolAddress((void**)&degOut, g_deg_out);
    cudaGetSymbolAddress((void**)&cnt, g_cnt);

    cudaMemsetAsync(degOut, 0, NN * sizeof(int));
    cudaMemsetAsync(cnt, 0, NN * sizeof(int));

    k_build<<<(EE / 2 + 255) / 256, 256>>>(es, ed);
    k_norm<<<(NN + 255) / 256, 256>>>();
    k_prep<<<1, 128>>>(b0, g0, be0, m0, v0, b1, g1, be1, m1, v1, b2);

    int gemm_blocks = (NN + BM - 1) / BM;   // 782
    int agg_blocks  = (NN + 7) / 8;         // warp per node

    k_gemm<<<gemm_blocks, 256>>>(x, W0, bufB);
    k_agg<<<agg_blocks, 256>>>(0, bufB, bufA, 1);
    k_gemm<<<gemm_blocks, 256>>>(bufA, W1, bufB);
    k_agg<<<agg_blocks, 256>>>(1, bufB, bufA, 1);
    k_gemm<<<gemm_blocks, 256>>>(bufA, W2, bufB);
    k_agg<<<agg_blocks, 256>>>(2, bufB, (float*)d_out, 0);
}

// round 4
// speedup vs baseline: 2.9902x; 1.4009x over previous
#include <cuda_runtime.h>
#include <cuda_fp16.h>

#define NN 100000
#define EE 1000000
#define DD 128
#define CAP 96

#define BM 128
#define ST 136          // smem stride in halfs (conflict-free)

// ---------------- scratch ----------------
__device__ __align__(128) __half g_h16[NN * DD];    // layer input activations (pre-scaled by norm_src), fp16
__device__ __align__(128) __half g_hs16[NN * DD];   // GEMM outputs (gather source), fp16
__device__ __align__(128) __half g_Wt[3 * DD * DD]; // transposed fp16 weights [n][k]
__device__ int   g_adj[NN * CAP];
__device__ int   g_deg_out[NN];
__device__ int   g_cnt[NN];
__device__ float g_norm_src[NN];
__device__ float g_norm_dst[NN];
__device__ __align__(16) float g_cs[3 * DD];
__device__ __align__(16) float g_cb[3 * DD];

// ---------------- graph preprocessing ----------------
__global__ void k_build(const int* __restrict__ es, const int* __restrict__ ed) {
    int i = (blockIdx.x * blockDim.x + threadIdx.x) * 2;
#pragma unroll
    for (int t = 0; t < 2; t++) {
        int e = i + t;
        if (e < EE) {
            int s = es[e], d = ed[e];
            atomicAdd(&g_deg_out[s], 1);
            int slot = atomicAdd(&g_cnt[d], 1);
            if (slot < CAP) g_adj[d * CAP + slot] = s;
        }
    }
}

__global__ void k_norm() {
    int i = blockIdx.x * blockDim.x + threadIdx.x;
    if (i < NN) {
        int dout = g_deg_out[i]; if (dout < 1) dout = 1;
        int din  = g_cnt[i];     if (din  < 1) din  = 1;
        g_norm_src[i] = rsqrtf((float)dout);
        g_norm_dst[i] = rsqrtf((float)din);
    }
}

__global__ void k_prep(const float* __restrict__ b0, const float* __restrict__ g0,
                       const float* __restrict__ be0, const float* __restrict__ m0,
                       const float* __restrict__ v0,
                       const float* __restrict__ b1, const float* __restrict__ g1,
                       const float* __restrict__ be1, const float* __restrict__ m1,
                       const float* __restrict__ v1,
                       const float* __restrict__ b2) {
    int j = threadIdx.x;
    if (j < DD) {
        float s0 = g0[j] * rsqrtf(v0[j] + 1e-5f);
        g_cs[j] = s0;
        g_cb[j] = (b0[j] - m0[j]) * s0 + be0[j];
        float s1 = g1[j] * rsqrtf(v1[j] + 1e-5f);
        g_cs[DD + j] = s1;
        g_cb[DD + j] = (b1[j] - m1[j]) * s1 + be1[j];
        g_cs[2 * DD + j] = 1.0f;
        g_cb[2 * DD + j] = b2[j];
    }
}

// transpose + convert weights: Wt[l][n*DD + k] = (half)W_l[k*DD + n]
__global__ void k_wprep(const float* __restrict__ W0, const float* __restrict__ W1,
                        const float* __restrict__ W2) {
    int i = blockIdx.x * blockDim.x + threadIdx.x;
    if (i < 3 * DD * DD) {
        int l = i / (DD * DD);
        int r = i - l * DD * DD;
        int n = r / DD;
        int k = r - n * DD;
        const float* W = (l == 0) ? W0 : (l == 1) ? W1 : W2;
        g_Wt[l * DD * DD + n * DD + k] = __float2half(W[k * DD + n]);
    }
}

// ---------------- fp16 mma helper ----------------
__device__ __forceinline__ void mma_f16(float c[4], const unsigned a[4], const unsigned b[2]) {
    asm volatile(
        "mma.sync.aligned.m16n8k16.row.col.f32.f16.f16.f32 "
        "{%0,%1,%2,%3}, {%4,%5,%6,%7}, {%8,%9}, {%0,%1,%2,%3};"
        : "+f"(c[0]), "+f"(c[1]), "+f"(c[2]), "+f"(c[3])
        : "r"(a[0]), "r"(a[1]), "r"(a[2]), "r"(a[3]), "r"(b[0]), "r"(b[1]));
}

// ---------------- GEMM core (fp16 tensor cores, whole-K in smem) ----------------
// As: [128 rows][ST] halfs (row-major k). Bs: [128 cols][ST] halfs ([n][k] layout).
__device__ __forceinline__ void gemm_core(const __half* As, const __half* Bs,
                                          __half* __restrict__ C16, int row0,
                                          int warp, int lane) {
    int wr = warp >> 1, wc = warp & 1;
    int g = lane >> 2, tig = lane & 3;
    int rm = wr * 32, cbase = wc * 64;

    float acc[2][8][4];
#pragma unroll
    for (int t = 0; t < 2; t++)
#pragma unroll
        for (int c = 0; c < 8; c++)
#pragma unroll
            for (int r = 0; r < 4; r++) acc[t][c][r] = 0.f;

#pragma unroll
    for (int ks = 0; ks < 8; ks++) {
        int kk = ks * 16;
        unsigned af[2][4];
#pragma unroll
        for (int t = 0; t < 2; t++) {
            int rbase = rm + t * 16 + g;
            af[t][0] = *(const unsigned*)&As[(rbase)     * ST + kk + 2 * tig];
            af[t][1] = *(const unsigned*)&As[(rbase + 8) * ST + kk + 2 * tig];
            af[t][2] = *(const unsigned*)&As[(rbase)     * ST + kk + 8 + 2 * tig];
            af[t][3] = *(const unsigned*)&As[(rbase + 8) * ST + kk + 8 + 2 * tig];
        }
        unsigned bf[8][2];
#pragma unroll
        for (int c = 0; c < 8; c++) {
            int col = cbase + c * 8 + g;
            bf[c][0] = *(const unsigned*)&Bs[col * ST + kk + 2 * tig];
            bf[c][1] = *(const unsigned*)&Bs[col * ST + kk + 8 + 2 * tig];
        }
#pragma unroll
        for (int t = 0; t < 2; t++)
#pragma unroll
            for (int c = 0; c < 8; c++)
                mma_f16(acc[t][c], af[t], bf[c]);
    }

    // epilogue: store fp16
#pragma unroll
    for (int t = 0; t < 2; t++) {
        int r_lo = row0 + rm + t * 16 + g;
        int r_hi = r_lo + 8;
#pragma unroll
        for (int c = 0; c < 8; c++) {
            int col = cbase + c * 8 + 2 * tig;
            if (r_lo < NN)
                *(__half2*)&C16[(long)r_lo * DD + col] = __floats2half2_rn(acc[t][c][0], acc[t][c][1]);
            if (r_hi < NN)
                *(__half2*)&C16[(long)r_hi * DD + col] = __floats2half2_rn(acc[t][c][2], acc[t][c][3]);
        }
    }
}

// layer 0: A = x (fp32), scaled by norm_src, converted to fp16
__global__ __launch_bounds__(256, 2) void k_gemm0(const float* __restrict__ A,
                                                  const __half* __restrict__ Wt,
                                                  __half* __restrict__ C16) {
    extern __shared__ __half smem[];
    __half* As = smem;
    __half* Bs = smem + BM * ST;

    int tid = threadIdx.x;
    int row0 = blockIdx.x * BM;

    // A: 128x128 fp32 -> scale -> fp16
#pragma unroll
    for (int it = 0; it < 16; it++) {
        int f = tid + it * 256;           // 0..4095
        int r = f >> 5;                   // 0..127
        int c4 = (f & 31) * 4;            // 0..124
        int grow = row0 + r;
        int gr = (grow < NN) ? grow : (NN - 1);
        float4 v = *(const float4*)&A[(long)gr * DD + c4];
        float s = g_norm_src[gr];
        __half2 h01 = __floats2half2_rn(v.x * s, v.y * s);
        __half2 h23 = __floats2half2_rn(v.z * s, v.w * s);
        *(__half2*)&As[r * ST + c4]     = h01;
        *(__half2*)&As[r * ST + c4 + 2] = h23;
    }
    // B: Wt [n][k] fp16 straight copy
#pragma unroll
    for (int it = 0; it < 8; it++) {
        int f = tid + it * 256;           // 0..2047
        int n = f >> 4;
        int s8 = (f & 15) * 8;
        *(uint4*)&Bs[n * ST + s8] = *(const uint4*)&Wt[n * DD + s8];
    }
    __syncthreads();
    gemm_core(As, Bs, C16, row0, tid >> 5, tid & 31);
}

// layers 1,2: A = g_h16 (fp16, already scaled by norm_src)
__global__ __launch_bounds__(256, 2) void k_gemm16(const __half* __restrict__ A,
                                                   const __half* __restrict__ Wt,
                                                   __half* __restrict__ C16) {
    extern __shared__ __half smem[];
    __half* As = smem;
    __half* Bs = smem + BM * ST;

    int tid = threadIdx.x;
    int row0 = blockIdx.x * BM;

#pragma unroll
    for (int it = 0; it < 8; it++) {
        int f = tid + it * 256;           // 0..2047
        int r = f >> 4;
        int s8 = (f & 15) * 8;
        int grow = row0 + r;
        int gr = (grow < NN) ? grow : (NN - 1);
        *(uint4*)&As[r * ST + s8] = *(const uint4*)&A[(long)gr * DD + s8];
    }
#pragma unroll
    for (int it = 0; it < 8; it++) {
        int f = tid + it * 256;
        int n = f >> 4;
        int s8 = (f & 15) * 8;
        *(uint4*)&Bs[n * ST + s8] = *(const uint4*)&Wt[n * DD + s8];
    }
    __syncthreads();
    gemm_core(As, Bs, C16, row0, tid >> 5, tid & 31);
}

// ---------------- Aggregate + fused epilogue: one warp per dst node ----------------
// mode 0/1: store fp16 (with relu and *norm_src fold) to g_h16; mode 2: fp32 to out
__global__ __launch_bounds__(256) void k_agg(int layer, int mode,
                                             const __half* __restrict__ hs,
                                             float* __restrict__ out) {
    int w    = (blockIdx.x * blockDim.x + threadIdx.x) >> 5;
    int lane = threadIdx.x & 31;
    if (w >= NN) return;

    int cnt = g_cnt[w]; if (cnt > CAP) cnt = CAP;
    const int* lst = &g_adj[w * CAP];

    float4 acc = make_float4(0.f, 0.f, 0.f, 0.f);
    int off = lane * 4;
    int e = 0;
    for (; e + 4 <= cnt; e += 4) {
        int s0 = lst[e], s1 = lst[e + 1], s2 = lst[e + 2], s3 = lst[e + 3];
        uint2 u0 = *(const uint2*)&hs[(long)s0 * DD + off];
        uint2 u1 = *(const uint2*)&hs[(long)s1 * DD + off];
        uint2 u2 = *(const uint2*)&hs[(long)s2 * DD + off];
        uint2 u3 = *(const uint2*)&hs[(long)s3 * DD + off];
#pragma unroll
        for (int q = 0; q < 4; q++) {
            uint2 u = (q == 0) ? u0 : (q == 1) ? u1 : (q == 2) ? u2 : u3;
            float2 f01 = __half22float2(*(__half2*)&u.x);
            float2 f23 = __half22float2(*(__half2*)&u.y);
            acc.x += f01.x; acc.y += f01.y; acc.z += f23.x; acc.w += f23.y;
        }
    }
    for (; e < cnt; e++) {
        int s = lst[e];
        uint2 u = *(const uint2*)&hs[(long)s * DD + off];
        float2 f01 = __half22float2(*(__half2*)&u.x);
        float2 f23 = __half22float2(*(__half2*)&u.y);
        acc.x += f01.x; acc.y += f01.y; acc.z += f23.x; acc.w += f23.y;
    }

    float nd = g_norm_dst[w];
    int jb = layer * DD + off;
    float4 cs = *(const float4*)&g_cs[jb];
    float4 cb = *(const float4*)&g_cb[jb];
    float4 r;
    r.x = acc.x * nd * cs.x + cb.x;
    r.y = acc.y * nd * cs.y + cb.y;
    r.z = acc.z * nd * cs.z + cb.z;
    r.w = acc.w * nd * cs.w + cb.w;

    if (mode < 2) {
        float ns = g_norm_src[w];
        r.x = fmaxf(r.x, 0.f) * ns;
        r.y = fmaxf(r.y, 0.f) * ns;
        r.z = fmaxf(r.z, 0.f) * ns;
        r.w = fmaxf(r.w, 0.f) * ns;
        __half2 h01 = __floats2half2_rn(r.x, r.y);
        __half2 h23 = __floats2half2_rn(r.z, r.w);
        uint2 u;
        u.x = *(unsigned*)&h01;
        u.y = *(unsigned*)&h23;
        *(uint2*)&g_h16[(long)w * DD + off] = u;
    } else {
        ((float4*)out)[w * 32 + lane] = r;
    }
}

// ---------------- launch ----------------
extern "C" void kernel_launch(void* const* d_in, const int* in_sizes, int n_in,
                              void* d_out, int out_size) {
    const float* x   = (const float*)d_in[0];
    const int*   es  = (const int*)d_in[1];
    const int*   ed  = (const int*)d_in[2];
    const float* W0  = (const float*)d_in[3];
    const float* b0  = (const float*)d_in[4];
    const float* W1  = (const float*)d_in[5];
    const float* b1  = (const float*)d_in[6];
    const float* W2  = (const float*)d_in[7];
    const float* b2  = (const float*)d_in[8];
    const float* g0  = (const float*)d_in[9];
    const float* be0 = (const float*)d_in[10];
    const float* m0  = (const float*)d_in[11];
    const float* v0  = (const float*)d_in[12];
    const float* g1  = (const float*)d_in[13];
    const float* be1 = (const float*)d_in[14];
    const float* m1  = (const float*)d_in[15];
    const float* v1  = (const float*)d_in[16];

    __half *h16, *hs16, *Wt;
    void *degOut, *cnt;
    cudaGetSymbolAddress((void**)&h16, g_h16);
    cudaGetSymbolAddress((void**)&hs16, g_hs16);
    cudaGetSymbolAddress((void**)&Wt, g_Wt);
    cudaGetSymbolAddress(&degOut, g_deg_out);
    cudaGetSymbolAddress(&cnt, g_cnt);

    const int smem_bytes = 2 * BM * ST * (int)sizeof(__half);  // 69632
    cudaFuncSetAttribute(k_gemm0,  cudaFuncAttributeMaxDynamicSharedMemorySize, smem_bytes);
    cudaFuncSetAttribute(k_gemm16, cudaFuncAttributeMaxDynamicSharedMemorySize, smem_bytes);

    cudaMemsetAsync(degOut, 0, NN * sizeof(int));
    cudaMemsetAsync(cnt, 0, NN * sizeof(int));

    k_build<<<(EE / 2 + 255) / 256, 256>>>(es, ed);
    k_norm<<<(NN + 255) / 256, 256>>>();
    k_prep<<<1, 128>>>(b0, g0, be0, m0, v0, b1, g1, be1, m1, v1, b2);
    k_wprep<<<(3 * DD * DD + 255) / 256, 256>>>(W0, W1, W2);

    int gemm_blocks = (NN + BM - 1) / BM;   // 782
    int agg_blocks  = (NN + 7) / 8;

    k_gemm0 <<<gemm_blocks, 256, smem_bytes>>>(x, Wt, hs16);
    k_agg   <<<agg_blocks, 256>>>(0, 0, hs16, nullptr);
    k_gemm16<<<gemm_blocks, 256, smem_bytes>>>(h16, Wt + DD * DD, hs16);
    k_agg   <<<agg_blocks, 256>>>(1, 1, hs16, nullptr);
    k_gemm16<<<gemm_blocks, 256, smem_bytes>>>(h16, Wt + 2 * DD * DD, hs16);
    k_agg   <<<agg_blocks, 256>>>(2, 2, hs16, (float*)d_out);
}